// round 15
// baseline (speedup 1.0000x reference)
#include <cuda_runtime.h>
#include <cuda_fp16.h>
#include <math.h>
#include <stdint.h>

#define NB    8
#define LQ    1000
#define DM    256
#define NH    8
#define DH    32
#define NLV   4
#define NPT   4
#define LEN_IN 21760
#define DFFN  1024
#define NQ    (NB*LQ)    /* 8000 */
#define NSRC  (NB*LEN_IN) /* 174080 */

// ---------------- fp32 scratch ---------------------------------------------
__device__ float g_proj[NQ*DM];
__device__ float g_tgt2[NQ*DM];
__device__ float g_tgt3[NQ*DM];
__device__ float g_offaw[NQ*384];
__device__ float g_cbias[384];

// ---------------- fp16 scratch ----------------------------------------------
__device__ __half g_qk16[NQ*DM];
__device__ __half g_tgt16[NQ*DM];
__device__ __half g_qk2[NQ*512];
__device__ __half g_v2[NQ*DM];
__device__ __half g_att16[NQ*DM];
__device__ __half g_query16[NQ*DM];
__device__ __half g_tgt3_16[NQ*DM];
__device__ __half g_ca16[NQ*DM];
__device__ __half g_ffn16[NQ*DFFN];
__device__ __half g_src16[(size_t)NSRC*DM];
__device__ __half g_value16[(size_t)NSRC*DM];

#define WTOT 1015808
#define OFF_SAIN  0
#define OFF_SAOUT 196608
#define OFF_OFFW  262144
#define OFF_VALW  360448
#define OFF_OUTPW 425984
#define OFF_FFN1  491520
#define OFF_FFN2  753664
__device__ __half g_w16[WTOT];

// =================== helpers ===============================================
__device__ __forceinline__ uint32_t smem_u32(const void* p) {
    uint32_t a;
    asm("{ .reg .u64 t; cvta.to.shared.u64 t, %1; cvt.u32.u64 %0, t; }" : "=r"(a) : "l"(p));
    return a;
}
__device__ __forceinline__ void ldmx4(uint32_t addr, uint32_t* r) {
    asm volatile("ldmatrix.sync.aligned.m8n8.x4.shared.b16 {%0,%1,%2,%3}, [%4];"
                 : "=r"(r[0]), "=r"(r[1]), "=r"(r[2]), "=r"(r[3]) : "r"(addr));
}
__device__ __forceinline__ void ldmx4t(uint32_t addr, uint32_t* r) {
    asm volatile("ldmatrix.sync.aligned.m8n8.x4.trans.shared.b16 {%0,%1,%2,%3}, [%4];"
                 : "=r"(r[0]), "=r"(r[1]), "=r"(r[2]), "=r"(r[3]) : "r"(addr));
}
__device__ __forceinline__ void mmah(float* d, const uint32_t* a, uint32_t b0, uint32_t b1) {
    asm volatile("mma.sync.aligned.m16n8k16.row.col.f32.f16.f16.f32 "
                 "{%0,%1,%2,%3}, {%4,%5,%6,%7}, {%8,%9}, {%0,%1,%2,%3};"
                 : "+f"(d[0]), "+f"(d[1]), "+f"(d[2]), "+f"(d[3])
                 : "r"(a[0]), "r"(a[1]), "r"(a[2]), "r"(a[3]), "r"(b0), "r"(b1));
}
__device__ __forceinline__ void cp16z(uint32_t dst, const void* src, bool v) {
    asm volatile("cp.async.cg.shared.global [%0], [%1], 16, %2;"
                 :: "r"(dst), "l"(src), "r"(v ? 16 : 0));
}
__device__ __forceinline__ float ex2f(float x) {
    float r; asm("ex2.approx.ftz.f32 %0, %1;" : "=f"(r) : "f"(x)); return r;
}

#define TCSTR 40   /* attention smem stride (elems), 80B rows */
#define GST   72   /* gemm smem stride (elems), 144B rows (BK=64) */

// =================== fp16 1-term GEMM, BK=64, 3-stage ring =================
// C[M,N] = A@B^T + bias. 128x128, 8 warps (32x64 warp tile).
// OUT: 0 = fp32, 1 = fp16 (opt RELU).
#define H1_A 0
#define H1_B 18432
#define H1_STAGE 36864
#define H1_NSTG 3
#define H1_SMEM (H1_NSTG*H1_STAGE)

__device__ __forceinline__ void stage_load_h1(
    uint32_t sb, const __half* A, const __half* B,
    int M, int N, int K, int rowBase, int colBase, int k0, int ldR, int ldC) {
    // 64 k-elems = 128B per row; each thread loads a 64B half-row of A and B
    int gr = rowBase + ldR; bool av = gr < M; if (!av) gr = 0;
    const char* pa = (const char*)(A + (size_t)gr * K + k0) + ldC;
    uint32_t da = sb + H1_A + ldR * 144 + ldC;
    cp16z(da, pa, av);        cp16z(da + 16, pa + 16, av);
    cp16z(da + 32, pa + 32, av); cp16z(da + 48, pa + 48, av);
    int gc = colBase + ldR; bool bv = gc < N; if (!bv) gc = 0;
    const char* pb = (const char*)(B + (size_t)gc * K + k0) + ldC;
    uint32_t db = sb + H1_B + ldR * 144 + ldC;
    cp16z(db, pb, bv);        cp16z(db + 16, pb + 16, bv);
    cp16z(db + 32, pb + 32, bv); cp16z(db + 48, pb + 48, bv);
    asm volatile("cp.async.commit_group;" ::: "memory");
}

template<bool RELU, int OUT>
__global__ __launch_bounds__(256)
void tc_gemm(const __half* __restrict__ A, const __half* __restrict__ B,
             const float* __restrict__ bias, float* __restrict__ Cf,
             __half* __restrict__ C16, int M, int N, int K) {
    extern __shared__ char smem[];
    const uint32_t sbase = smem_u32(smem);
    const int tid  = threadIdx.x;
    const int lane = tid & 31;
    const int wid  = tid >> 5;
    const int warpM = wid & 3;
    const int warpN = wid >> 2;
    const int rowBase = blockIdx.y * 128;
    const int colBase = blockIdx.x * 128;
    const int ldR = tid >> 1;
    const int ldC = (tid & 1) * 64;

    const int aRow = (lane & 15);
    const int aColOff = (lane >> 4) * 8;
    const int bRow = (lane & 7) + ((lane >> 4) & 1) * 8;
    const int bColOff = ((lane >> 3) & 1) * 8;

    float acc[2][8][4];
    #pragma unroll
    for (int mt = 0; mt < 2; mt++)
        #pragma unroll
        for (int nt = 0; nt < 8; nt++)
            #pragma unroll
            for (int i = 0; i < 4; i++) acc[mt][nt][i] = 0.f;

    const int KC = K >> 6;
    #pragma unroll
    for (int s = 0; s < H1_NSTG - 1; s++)
        if (s < KC)
            stage_load_h1(sbase + s * H1_STAGE, A, B, M, N, K,
                          rowBase, colBase, s << 6, ldR, ldC);

    int slot = 0;
    for (int c = 0; c < KC; c++) {
        asm volatile("cp.async.wait_group %0;" :: "n"(H1_NSTG - 2) : "memory");
        __syncthreads();
        if (c + H1_NSTG - 1 < KC) {
            int ps = slot + (H1_NSTG - 1); if (ps >= H1_NSTG) ps -= H1_NSTG;
            stage_load_h1(sbase + ps * H1_STAGE, A, B, M, N, K,
                          rowBase, colBase, (c + H1_NSTG - 1) << 6, ldR, ldC);
        }

        const uint32_t sb = sbase + slot * H1_STAGE;
        if (++slot == H1_NSTG) slot = 0;
        #pragma unroll
        for (int ks = 0; ks < 64; ks += 16) {
            uint32_t ah[2][4];
            #pragma unroll
            for (int mt = 0; mt < 2; mt++) {
                const int r0 = warpM * 32 + mt * 16;
                uint32_t off = (uint32_t)((r0 + aRow) * GST + ks + aColOff) * 2;
                ldmx4(sb + H1_A + off, ah[mt]);
            }
            uint32_t bh[4][4];
            #pragma unroll
            for (int nb = 0; nb < 4; nb++) {
                const int n0 = warpN * 64 + nb * 16;
                uint32_t off = (uint32_t)((n0 + bRow) * GST + ks + bColOff) * 2;
                ldmx4(sb + H1_B + off, bh[nb]);
            }
            #pragma unroll
            for (int mt = 0; mt < 2; mt++) {
                #pragma unroll
                for (int nt = 0; nt < 8; nt++) {
                    const int nb = nt >> 1, hi = (nt & 1) * 2;
                    mmah(acc[mt][nt], ah[mt], bh[nb][hi], bh[nb][hi+1]);
                }
            }
        }
    }

    #pragma unroll
    for (int mt = 0; mt < 2; mt++) {
        #pragma unroll
        for (int half = 0; half < 2; half++) {
            const int row = rowBase + warpM * 32 + mt * 16 + (lane >> 2) + half * 8;
            if (row < M) {
                #pragma unroll
                for (int nt = 0; nt < 8; nt++) {
                    const int col = colBase + warpN * 64 + nt * 8 + (lane & 3) * 2;
                    float ox = acc[mt][nt][half*2+0] + bias[col];
                    float oy = acc[mt][nt][half*2+1] + bias[col+1];
                    if (RELU) { ox = fmaxf(ox, 0.f); oy = fmaxf(oy, 0.f); }
                    if (OUT == 0) {
                        *(float2*)(Cf + (size_t)row * N + col) = make_float2(ox, oy);
                    } else {
                        *(__half2*)(C16 + (size_t)row * N + col) =
                            __half2(__float2half(ox), __float2half(oy));
                    }
                }
            }
        }
    }
}

// =================== fp16 tensor-core flash self-attention (R14) ===========
#define ATT_Q 0
#define ATT_KV(st) (10240 + (st)*10240)
#define ATT_K_O 0
#define ATT_V_O 5120
#define ATT_SMEM (10240 + 2*10240)
#define KSCALE 0.25503486f   /* log2(e)/sqrt(32) */

__global__ __launch_bounds__(256)
void attn_mma(const __half* __restrict__ qk2, const __half* __restrict__ v2,
              __half* __restrict__ oh) {
    extern __shared__ char smem[];
    const uint32_t sb = smem_u32(smem);
    const int tid = threadIdx.x;
    const int lane = tid & 31;
    const int w = tid >> 5;
    const int g = lane >> 2, t4 = lane & 3;
    const int qbase = blockIdx.x * 128;
    const int b = blockIdx.y >> 3, h = blockIdx.y & 7;

    {
        const int r = tid >> 1, cb = (tid & 1) * 32;
        const int gr = qbase + r;
        const bool v = gr < LQ;
        const size_t rowo = ((size_t)(b * LQ + (v ? gr : 0)) * 512 + h * 32) * 2;
        cp16z(sb + ATT_Q + r * 80 + cb,      (const char*)qk2 + rowo + cb, v);
        cp16z(sb + ATT_Q + r * 80 + cb + 16, (const char*)qk2 + rowo + cb + 16, v);
    }
    {
        const int r = tid >> 2, j = tid & 3;
        const bool v = r < LQ;
        const size_t ko = ((size_t)(b * LQ + (v ? r : 0)) * 512 + 256 + h * 32) * 2 + j * 16;
        const size_t vo = ((size_t)(b * LQ + (v ? r : 0)) * 256 + h * 32) * 2 + j * 16;
        cp16z(sb + ATT_KV(0) + ATT_K_O + r * 80 + j * 16, (const char*)qk2 + ko, v);
        cp16z(sb + ATT_KV(0) + ATT_V_O + r * 80 + j * 16, (const char*)v2 + vo, v);
    }
    asm volatile("cp.async.commit_group;" ::: "memory");

    float m0 = -1e30f, m1 = -1e30f, l0 = 0.f, l1 = 0.f;
    float o[4][4];
    #pragma unroll
    for (int vt = 0; vt < 4; vt++)
        #pragma unroll
        for (int i = 0; i < 4; i++) o[vt][i] = 0.f;

    uint32_t qh[2][4];
    const int bRow = (lane & 7) + ((lane >> 4) & 1) * 8;
    const int bColOff = ((lane >> 3) & 1) * 8;
    const int NT = (LQ + 63) / 64;

    for (int ti = 0; ti < NT; ti++) {
        asm volatile("cp.async.wait_group 0;" ::: "memory");
        __syncthreads();
        if (ti == 0) {
            #pragma unroll
            for (int kf = 0; kf < 2; kf++) {
                uint32_t off = (uint32_t)((w * 16 + (lane & 15)) * TCSTR + kf * 16 + (lane >> 4) * 8) * 2;
                ldmx4(sb + ATT_Q + off, qh[kf]);
            }
        }
        if (ti + 1 < NT) {
            const int kt = (ti + 1) * 64;
            const int r = tid >> 2, j = tid & 3;
            const int kr = kt + r;
            const bool v = kr < LQ;
            const size_t ko = ((size_t)(b * LQ + (v ? kr : 0)) * 512 + 256 + h * 32) * 2 + j * 16;
            const size_t vo = ((size_t)(b * LQ + (v ? kr : 0)) * 256 + h * 32) * 2 + j * 16;
            const uint32_t st = sb + ATT_KV((ti + 1) & 1);
            cp16z(st + ATT_K_O + r * 80 + j * 16, (const char*)qk2 + ko, v);
            cp16z(st + ATT_V_O + r * 80 + j * 16, (const char*)v2 + vo, v);
            asm volatile("cp.async.commit_group;" ::: "memory");
        }

        const uint32_t stg = sb + ATT_KV(ti & 1);
        const int kt = ti * 64;

        float s[8][4];
        #pragma unroll
        for (int nt = 0; nt < 8; nt++)
            #pragma unroll
            for (int i = 0; i < 4; i++) s[nt][i] = 0.f;
        #pragma unroll
        for (int kf = 0; kf < 2; kf++) {
            #pragma unroll
            for (int nb = 0; nb < 4; nb++) {
                uint32_t off = (uint32_t)((nb * 16 + bRow) * TCSTR + kf * 16 + bColOff) * 2;
                uint32_t kh[4];
                ldmx4(stg + ATT_K_O + off, kh);
                #pragma unroll
                for (int hf = 0; hf < 2; hf++) {
                    mmah(s[nb * 2 + hf], qh[kf], kh[hf*2], kh[hf*2+1]);
                }
            }
        }

        const int validTiles = min(8, (LQ - kt) >> 3);
        float tmax0 = -1e30f, tmax1 = -1e30f;
        #pragma unroll
        for (int nt = 0; nt < 8; nt++) {
            if (nt < validTiles) {
                s[nt][0] *= KSCALE; s[nt][1] *= KSCALE;
                s[nt][2] *= KSCALE; s[nt][3] *= KSCALE;
            } else {
                s[nt][0] = s[nt][1] = s[nt][2] = s[nt][3] = -1e30f;
            }
            tmax0 = fmaxf(tmax0, fmaxf(s[nt][0], s[nt][1]));
            tmax1 = fmaxf(tmax1, fmaxf(s[nt][2], s[nt][3]));
        }
        tmax0 = fmaxf(tmax0, __shfl_xor_sync(0xffffffffu, tmax0, 1));
        tmax0 = fmaxf(tmax0, __shfl_xor_sync(0xffffffffu, tmax0, 2));
        tmax1 = fmaxf(tmax1, __shfl_xor_sync(0xffffffffu, tmax1, 1));
        tmax1 = fmaxf(tmax1, __shfl_xor_sync(0xffffffffu, tmax1, 2));
        const float mn0 = fmaxf(m0, tmax0), mn1 = fmaxf(m1, tmax1);
        const float c0 = ex2f(m0 - mn0), c1 = ex2f(m1 - mn1);
        m0 = mn0; m1 = mn1;
        l0 *= c0; l1 *= c1;
        #pragma unroll
        for (int vt = 0; vt < 4; vt++) {
            o[vt][0] *= c0; o[vt][1] *= c0; o[vt][2] *= c1; o[vt][3] *= c1;
        }

        uint32_t ph[4][4];
        #pragma unroll
        for (int nt = 0; nt < 8; nt++) {
            float p0 = ex2f(s[nt][0] - mn0), p1 = ex2f(s[nt][1] - mn0);
            float p2 = ex2f(s[nt][2] - mn1), p3 = ex2f(s[nt][3] - mn1);
            l0 += p0 + p1; l1 += p2 + p3;
            const int ks = nt >> 1, base = (nt & 1) * 2;
            __half2 p01(__float2half(p0), __float2half(p1));
            __half2 p23(__float2half(p2), __float2half(p3));
            ph[ks][base+0] = *(uint32_t*)&p01;
            ph[ks][base+1] = *(uint32_t*)&p23;
        }

        #pragma unroll
        for (int ks = 0; ks < 4; ks++) {
            const int krow = ks * 16 + (lane & 7) + ((lane >> 3) & 1) * 8;
            #pragma unroll
            for (int nh = 0; nh < 2; nh++) {
                uint32_t off = (uint32_t)(krow * TCSTR + nh * 16 + (lane >> 4) * 8) * 2;
                uint32_t vh[4];
                ldmx4t(stg + ATT_V_O + off, vh);
                #pragma unroll
                for (int sub = 0; sub < 2; sub++) {
                    mmah(o[nh * 2 + sub], ph[ks], vh[sub*2], vh[sub*2+1]);
                }
            }
        }
    }

    l0 += __shfl_xor_sync(0xffffffffu, l0, 1);
    l0 += __shfl_xor_sync(0xffffffffu, l0, 2);
    l1 += __shfl_xor_sync(0xffffffffu, l1, 1);
    l1 += __shfl_xor_sync(0xffffffffu, l1, 2);
    const float inv0 = 1.f / l0, inv1 = 1.f / l1;
    const int r0 = qbase + w * 16 + g;
    const int r1 = r0 + 8;
    #pragma unroll
    for (int half = 0; half < 2; half++) {
        const int row = half ? r1 : r0;
        const float inv = half ? inv1 : inv0;
        if (row < LQ) {
            const size_t base = ((size_t)(b * LQ + row)) * DM + h * DH;
            #pragma unroll
            for (int vt = 0; vt < 4; vt++) {
                float vx = o[vt][half*2+0] * inv;
                float vy = o[vt][half*2+1] * inv;
                *(__half2*)(oh + base + vt * 8 + t4 * 2) =
                    __half2(__float2half(vx), __float2half(vy));
            }
        }
    }
}

// ---------------- weight converter (fp16 single) + combined bias -----------
__global__ void cvt_weights(const float* __restrict__ w0, const float* __restrict__ w1,
                            const float* __restrict__ w2, const float* __restrict__ w3,
                            const float* __restrict__ w4, const float* __restrict__ w5,
                            const float* __restrict__ w6, const float* __restrict__ w7,
                            const float* __restrict__ off_b, const float* __restrict__ aw_b,
                            __half* __restrict__ w16, float* __restrict__ cbias) {
    int i = blockIdx.x * blockDim.x + threadIdx.x;
    if (i < 384) cbias[i] = (i < 256) ? off_b[i] : aw_b[i - 256];
    if (i >= WTOT) return;
    const float* src; int local;
    if      (i < OFF_SAOUT) { src = w0; local = i; }
    else if (i < OFF_OFFW)  { src = w1; local = i - OFF_SAOUT; }
    else if (i < OFF_VALW)  { src = (i < 327680) ? w2 : w3; local = (i < 327680) ? i - OFF_OFFW : i - 327680; }
    else if (i < OFF_OUTPW) { src = w4; local = i - OFF_VALW; }
    else if (i < OFF_FFN1)  { src = w5; local = i - OFF_OUTPW; }
    else if (i < OFF_FFN2)  { src = w6; local = i - OFF_FFN1; }
    else                    { src = w7; local = i - OFF_FFN2; }
    w16[i] = __float2half(src[local]);
}

// ---------------- add + fp16 convert ---------------------------------------
__global__ void add_cvt_kernel(const float* __restrict__ a, const float* __restrict__ b,
                               __half* __restrict__ q16, __half* __restrict__ t16, int n4) {
    int i = blockIdx.x * blockDim.x + threadIdx.x;
    if (i >= n4) return;
    float4 x = ((const float4*)a)[i];
    float4 y = ((const float4*)b)[i];
    *(__half2*)(q16 + i*4)     = __half2(__float2half(x.x + y.x), __float2half(x.y + y.y));
    *(__half2*)(q16 + i*4 + 2) = __half2(__float2half(x.z + y.z), __float2half(x.w + y.w));
    *(__half2*)(t16 + i*4)     = __half2(__float2half(x.x), __float2half(x.y));
    *(__half2*)(t16 + i*4 + 2) = __half2(__float2half(x.z), __float2half(x.w));
}

// ---------------- fp32 -> fp16 converter ------------------------------------
__global__ void cvt_f16_kernel(const float* __restrict__ a, __half* __restrict__ o, int n4) {
    int i = blockIdx.x * blockDim.x + threadIdx.x;
    if (i >= n4) return;
    float4 x = ((const float4*)a)[i];
    *(__half2*)(o + i*4)     = __half2(__float2half(x.x), __float2half(x.y));
    *(__half2*)(o + i*4 + 2) = __half2(__float2half(x.z), __float2half(x.w));
}

// ---------------- LayerNorm(x+res) -> fp32 (+ optional fp16 of out+pos) ----
__global__ __launch_bounds__(256)
void ln_kernel(const float* __restrict__ x, const float* __restrict__ res,
               const float* __restrict__ g, const float* __restrict__ bta,
               float* __restrict__ out,
               const float* __restrict__ pos, __half* __restrict__ o16) {
    __shared__ float red[8];
    const int row = blockIdx.x, t = threadIdx.x;
    const size_t idx = (size_t)row * DM + t;
    float v = x[idx] + res[idx];

    float s = v;
    #pragma unroll
    for (int o = 16; o; o >>= 1) s += __shfl_xor_sync(0xffffffffu, s, o);
    if ((t & 31) == 0) red[t >> 5] = s;
    __syncthreads();
    float mean = 0.f;
    #pragma unroll
    for (int i = 0; i < 8; i++) mean += red[i];
    mean *= (1.f / DM);
    __syncthreads();

    float d = v - mean;
    float s2 = d * d;
    #pragma unroll
    for (int o = 16; o; o >>= 1) s2 += __shfl_xor_sync(0xffffffffu, s2, o);
    if ((t & 31) == 0) red[t >> 5] = s2;
    __syncthreads();
    float var = 0.f;
    #pragma unroll
    for (int i = 0; i < 8; i++) var += red[i];
    var *= (1.f / DM);

    float o = d * rsqrtf(var + 1e-5f) * g[t] + bta[t];
    out[idx] = o;
    if (o16) {
        float tq = pos ? o + pos[idx] : o;
        o16[idx] = __float2half(tq);
    }
}

// ---------------- MS-deformable sampling (fused aw softmax, half2) ---------
__global__ __launch_bounds__(128)
void deform_kernel(const __half* __restrict__ value, const float* __restrict__ offaw,
                   const float* __restrict__ ref, __half* __restrict__ o16) {
    __shared__ float saw[8][16];
    const int qidx = blockIdx.x;
    const int b = qidx / LQ;
    const int h = threadIdx.y;          // 0..7
    const int d2 = threadIdx.x;         // 0..15

    const size_t oq = (size_t)qidx;
    const float* offp = offaw + oq * 384;

    // fused softmax over 16 logits per head (intra-16-lane shuffles)
    {
        float logit = offp[256 + h * 16 + d2];
        float mx = logit;
        #pragma unroll
        for (int o = 8; o; o >>= 1) mx = fmaxf(mx, __shfl_xor_sync(0xffffffffu, mx, o));
        float e = __expf(logit - mx);
        float sm = e;
        #pragma unroll
        for (int o = 8; o; o >>= 1) sm += __shfl_xor_sync(0xffffffffu, sm, o);
        saw[h][d2] = e / sm;
    }
    __syncthreads();

    const int starts[4] = {0, 16384, 20480, 21504};
    const int Wi[4]     = {128, 64, 32, 16};

    const __half2* vb = (const __half2*)(value + (size_t)b * LEN_IN * DM + h * DH) + d2;
    float accx = 0.f, accy = 0.f;

    #pragma unroll
    for (int lvl = 0; lvl < NLV; lvl++) {
        const float W = (float)Wi[lvl];
        const int   Wl = Wi[lvl];
        const int   st = starts[lvl];
        const float rx = ref[(oq * NLV + lvl) * 2 + 0];
        const float ry = ref[(oq * NLV + lvl) * 2 + 1];
        #pragma unroll
        for (int p = 0; p < NPT; p++) {
            const int oidx = ((h * NLV + lvl) * NPT + p) * 2;
            const float ox = offp[oidx + 0];
            const float oy = offp[oidx + 1];
            const float a  = saw[h][lvl * 4 + p];
            const float x = (rx + ox / W) * W - 0.5f;
            const float y = (ry + oy / W) * W - 0.5f;
            const float x0f = floorf(x), y0f = floorf(y);
            const float lx = x - x0f, ly = y - y0f;
            const int x0 = (int)x0f, y0 = (int)y0f;

            const float w00 = a * (1.f - ly) * (1.f - lx);
            const float w01 = a * (1.f - ly) * lx;
            const float w10 = a * ly * (1.f - lx);
            const float w11 = a * ly * lx;

            const bool xv0 = (x0 >= 0) & (x0 < Wl);
            const bool xv1 = (x0 + 1 >= 0) & (x0 + 1 < Wl);
            const bool yv0 = (y0 >= 0) & (y0 < Wl);
            const bool yv1 = (y0 + 1 >= 0) & (y0 + 1 < Wl);

            if (yv0 & xv0) { float2 v = __half22float2(vb[(size_t)(st + y0 * Wl + x0) * 128]); accx = fmaf(w00, v.x, accx); accy = fmaf(w00, v.y, accy); }
            if (yv0 & xv1) { float2 v = __half22float2(vb[(size_t)(st + y0 * Wl + x0 + 1) * 128]); accx = fmaf(w01, v.x, accx); accy = fmaf(w01, v.y, accy); }
            if (yv1 & xv0) { float2 v = __half22float2(vb[(size_t)(st + (y0 + 1) * Wl + x0) * 128]); accx = fmaf(w10, v.x, accx); accy = fmaf(w10, v.y, accy); }
            if (yv1 & xv1) { float2 v = __half22float2(vb[(size_t)(st + (y0 + 1) * Wl + x0 + 1) * 128]); accx = fmaf(w11, v.x, accx); accy = fmaf(w11, v.y, accy); }
        }
    }
    *(__half2*)(o16 + oq * DM + h * DH + d2 * 2) =
        __half2(__float2half(accx), __float2half(accy));
}

// ---------------- host-side orchestration ----------------------------------
static inline void gemm_f32(const __half* A, const __half* B, const float* bias,
                            float* Cf, int M, int N, int K) {
    dim3 grid(N / 128, (M + 127) / 128);
    tc_gemm<false, 0><<<grid, 256, H1_SMEM>>>(A, B, bias, Cf, 0, M, N, K);
}
static inline void gemm_f16(const __half* A, const __half* B, const float* bias,
                            __half* C16, int M, int N, int K, bool relu) {
    dim3 grid(N / 128, (M + 127) / 128);
    if (relu) tc_gemm<true, 1><<<grid, 256, H1_SMEM>>>(A, B, bias, 0, C16, M, N, K);
    else      tc_gemm<false, 1><<<grid, 256, H1_SMEM>>>(A, B, bias, 0, C16, M, N, K);
}

extern "C" void kernel_launch(void* const* d_in, const int* in_sizes, int n_in,
                              void* d_out, int out_size) {
    (void)in_sizes; (void)n_in; (void)out_size;
    const float* tgt       = (const float*)d_in[0];
    const float* query_pos = (const float*)d_in[1];
    const float* refpts    = (const float*)d_in[2];
    const float* src       = (const float*)d_in[3];
    const float* sa_in_b   = (const float*)d_in[7];
    const float* sa_out_b  = (const float*)d_in[9];
    const float* norm2_g   = (const float*)d_in[10];
    const float* norm2_b   = (const float*)d_in[11];
    const float* off_b     = (const float*)d_in[13];
    const float* aw_b      = (const float*)d_in[15];
    const float* val_b     = (const float*)d_in[17];
    const float* outp_b    = (const float*)d_in[19];
    const float* norm1_g   = (const float*)d_in[20];
    const float* norm1_b   = (const float*)d_in[21];
    const float* ffn_b1    = (const float*)d_in[23];
    const float* ffn_b2    = (const float*)d_in[25];
    const float* norm3_g   = (const float*)d_in[26];
    const float* norm3_b   = (const float*)d_in[27];
    float* out = (float*)d_out;

    cudaFuncSetAttribute(tc_gemm<false,0>, cudaFuncAttributeMaxDynamicSharedMemorySize, H1_SMEM);
    cudaFuncSetAttribute(tc_gemm<false,1>, cudaFuncAttributeMaxDynamicSharedMemorySize, H1_SMEM);
    cudaFuncSetAttribute(tc_gemm<true,1>,  cudaFuncAttributeMaxDynamicSharedMemorySize, H1_SMEM);
    cudaFuncSetAttribute(attn_mma, cudaFuncAttributeMaxDynamicSharedMemorySize, ATT_SMEM);

    void* p;
    #define SYMF(name) cudaGetSymbolAddress(&p, name); float* name##_p = (float*)p;
    #define SYMH(name) cudaGetSymbolAddress(&p, name); __half* name##_p = (__half*)p;
    SYMF(g_proj) SYMF(g_tgt2) SYMF(g_tgt3) SYMF(g_offaw) SYMF(g_cbias)
    SYMH(g_qk16) SYMH(g_tgt16) SYMH(g_qk2) SYMH(g_v2)
    SYMH(g_att16) SYMH(g_query16) SYMH(g_tgt3_16) SYMH(g_ca16) SYMH(g_ffn16)
    SYMH(g_src16) SYMH(g_value16) SYMH(g_w16)
    #undef SYMF
    #undef SYMH

    // 0) weight + input conversions
    cvt_weights<<<(WTOT + 255)/256, 256>>>(
        (const float*)d_in[6], (const float*)d_in[8], (const float*)d_in[12],
        (const float*)d_in[14], (const float*)d_in[16], (const float*)d_in[18],
        (const float*)d_in[22], (const float*)d_in[24],
        off_b, aw_b, g_w16_p, g_cbias_p);
    const int n4 = NQ * DM / 4;
    add_cvt_kernel<<<(n4 + 255)/256, 256>>>(tgt, query_pos, g_qk16_p, g_tgt16_p, n4);
    const int ns4 = (int)((size_t)NSRC * DM / 4);
    cvt_f16_kernel<<<(ns4 + 255)/256, 256>>>(src, g_src16_p, ns4);

    // 1) self-attn
    gemm_f16(g_qk16_p, g_w16_p + OFF_SAIN, sa_in_b, g_qk2_p, NQ, 512, DM, false);
    gemm_f16(g_tgt16_p, g_w16_p + OFF_SAIN + 131072, sa_in_b + 2*DM, g_v2_p, NQ, DM, DM, false);
    attn_mma<<<dim3(8, NB * NH), 256, ATT_SMEM>>>(g_qk2_p, g_v2_p, g_att16_p);
    gemm_f32(g_att16_p, g_w16_p + OFF_SAOUT, sa_out_b, g_proj_p, NQ, DM, DM);
    ln_kernel<<<NQ, DM>>>(tgt, g_proj_p, norm2_g, norm2_b, g_tgt2_p, query_pos, g_query16_p);

    // 2) cross-attn (aw softmax fused into deform)
    gemm_f16(g_src16_p, g_w16_p + OFF_VALW, val_b, g_value16_p, NSRC, DM, DM, false);
    gemm_f32(g_query16_p, g_w16_p + OFF_OFFW, g_cbias_p, g_offaw_p, NQ, 384, DM);
    deform_kernel<<<NQ, dim3(16, 8)>>>(g_value16_p, g_offaw_p, refpts, g_ca16_p);
    gemm_f32(g_ca16_p, g_w16_p + OFF_OUTPW, outp_b, g_proj_p, NQ, DM, DM);
    ln_kernel<<<NQ, DM>>>(g_tgt2_p, g_proj_p, norm1_g, norm1_b, g_tgt3_p, nullptr, g_tgt3_16_p);

    // 3) FFN
    gemm_f16(g_tgt3_16_p, g_w16_p + OFF_FFN1, ffn_b1, g_ffn16_p, NQ, DFFN, DM, true);
    gemm_f32(g_ffn16_p, g_w16_p + OFF_FFN2, ffn_b2, g_proj_p, NQ, DM, DFFN);
    ln_kernel<<<NQ, DM>>>(g_tgt3_p, g_proj_p, norm3_g, norm3_b, out, nullptr, nullptr);
}

// round 16
// speedup vs baseline: 1.0336x; 1.0336x over previous
#include <cuda_runtime.h>
#include <cuda_fp16.h>
#include <math.h>
#include <stdint.h>

#define NB    8
#define LQ    1000
#define DM    256
#define NH    8
#define DH    32
#define NLV   4
#define NPT   4
#define LEN_IN 21760
#define DFFN  1024
#define NQ    (NB*LQ)    /* 8000 */
#define NSRC  (NB*LEN_IN) /* 174080 */

// ---------------- fp32 scratch ---------------------------------------------
__device__ float g_proj[NQ*DM];
__device__ float g_tgt2[NQ*DM];
__device__ float g_tgt3[NQ*DM];
__device__ float g_offaw[NQ*384];
__device__ float g_cbias[384];

// ---------------- fp16 scratch ----------------------------------------------
__device__ __half g_qk16[NQ*DM];
__device__ __half g_tgt16[NQ*DM];
__device__ __half g_qk2[NQ*512];
__device__ __half g_v2[NQ*DM];
__device__ __half g_att16[NQ*DM];
__device__ __half g_query16[NQ*DM];
__device__ __half g_tgt3_16[NQ*DM];
__device__ __half g_ca16[NQ*DM];
__device__ __half g_ffn16[NQ*DFFN];
__device__ __half g_src16[(size_t)NSRC*DM];
__device__ __half g_value16[(size_t)NSRC*DM];

#define WTOT 1015808
#define OFF_SAIN  0
#define OFF_SAOUT 196608
#define OFF_OFFW  262144
#define OFF_VALW  360448
#define OFF_OUTPW 425984
#define OFF_FFN1  491520
#define OFF_FFN2  753664
__device__ __half g_w16[WTOT];

// =================== helpers ===============================================
__device__ __forceinline__ uint32_t smem_u32(const void* p) {
    uint32_t a;
    asm("{ .reg .u64 t; cvta.to.shared.u64 t, %1; cvt.u32.u64 %0, t; }" : "=r"(a) : "l"(p));
    return a;
}
__device__ __forceinline__ void ldmx4(uint32_t addr, uint32_t* r) {
    asm volatile("ldmatrix.sync.aligned.m8n8.x4.shared.b16 {%0,%1,%2,%3}, [%4];"
                 : "=r"(r[0]), "=r"(r[1]), "=r"(r[2]), "=r"(r[3]) : "r"(addr));
}
__device__ __forceinline__ void ldmx4t(uint32_t addr, uint32_t* r) {
    asm volatile("ldmatrix.sync.aligned.m8n8.x4.trans.shared.b16 {%0,%1,%2,%3}, [%4];"
                 : "=r"(r[0]), "=r"(r[1]), "=r"(r[2]), "=r"(r[3]) : "r"(addr));
}
__device__ __forceinline__ void mmah(float* d, const uint32_t* a, uint32_t b0, uint32_t b1) {
    asm volatile("mma.sync.aligned.m16n8k16.row.col.f32.f16.f16.f32 "
                 "{%0,%1,%2,%3}, {%4,%5,%6,%7}, {%8,%9}, {%0,%1,%2,%3};"
                 : "+f"(d[0]), "+f"(d[1]), "+f"(d[2]), "+f"(d[3])
                 : "r"(a[0]), "r"(a[1]), "r"(a[2]), "r"(a[3]), "r"(b0), "r"(b1));
}
__device__ __forceinline__ void cp16z(uint32_t dst, const void* src, bool v) {
    asm volatile("cp.async.cg.shared.global [%0], [%1], 16, %2;"
                 :: "r"(dst), "l"(src), "r"(v ? 16 : 0));
}
__device__ __forceinline__ float ex2f(float x) {
    float r; asm("ex2.approx.ftz.f32 %0, %1;" : "=f"(r) : "f"(x)); return r;
}

#define TCSTR 40

// =================== fp16 1-term GEMM, BK=32, 3-stage ring (R14) ===========
// C[M,N] = A@B^T + bias. 128x128, 8 warps (32x64 warp tile).
// OUT: 0 = fp32, 1 = fp16 (opt RELU).
#define H1_A 0
#define H1_B 10240
#define H1_STAGE 20480
#define H1_NSTG 3
#define H1_SMEM (H1_NSTG*H1_STAGE)

__device__ __forceinline__ void stage_load_h1(
    uint32_t sb, const __half* A, const __half* B,
    int M, int N, int K, int rowBase, int colBase, int k0, int ldR, int ldC) {
    int gr = rowBase + ldR; bool av = gr < M; if (!av) gr = 0;
    const char* pa = (const char*)(A + (size_t)gr * K + k0) + ldC;
    uint32_t da = sb + H1_A + ldR * 80 + ldC;
    cp16z(da, pa, av);        cp16z(da + 16, pa + 16, av);
    int gc = colBase + ldR; bool bv = gc < N; if (!bv) gc = 0;
    const char* pb = (const char*)(B + (size_t)gc * K + k0) + ldC;
    uint32_t db = sb + H1_B + ldR * 80 + ldC;
    cp16z(db, pb, bv);        cp16z(db + 16, pb + 16, bv);
    asm volatile("cp.async.commit_group;" ::: "memory");
}

template<bool RELU, int OUT>
__global__ __launch_bounds__(256)
void tc_gemm(const __half* __restrict__ A, const __half* __restrict__ B,
             const float* __restrict__ bias, float* __restrict__ Cf,
             __half* __restrict__ C16, int M, int N, int K) {
    extern __shared__ char smem[];
    const uint32_t sbase = smem_u32(smem);
    const int tid  = threadIdx.x;
    const int lane = tid & 31;
    const int wid  = tid >> 5;
    const int warpM = wid & 3;
    const int warpN = wid >> 2;
    const int rowBase = blockIdx.y * 128;
    const int colBase = blockIdx.x * 128;
    const int ldR = tid >> 1;
    const int ldC = (tid & 1) * 32;

    const int aRow = (lane & 15);
    const int aColOff = (lane >> 4) * 8;
    const int bRow = (lane & 7) + ((lane >> 4) & 1) * 8;
    const int bColOff = ((lane >> 3) & 1) * 8;

    float acc[2][8][4];
    #pragma unroll
    for (int mt = 0; mt < 2; mt++)
        #pragma unroll
        for (int nt = 0; nt < 8; nt++)
            #pragma unroll
            for (int i = 0; i < 4; i++) acc[mt][nt][i] = 0.f;

    const int KC = K >> 5;
    #pragma unroll
    for (int s = 0; s < H1_NSTG - 1; s++)
        if (s < KC)
            stage_load_h1(sbase + s * H1_STAGE, A, B, M, N, K,
                          rowBase, colBase, s << 5, ldR, ldC);

    int slot = 0;
    for (int c = 0; c < KC; c++) {
        asm volatile("cp.async.wait_group %0;" :: "n"(H1_NSTG - 2) : "memory");
        __syncthreads();
        if (c + H1_NSTG - 1 < KC) {
            int ps = slot + (H1_NSTG - 1); if (ps >= H1_NSTG) ps -= H1_NSTG;
            stage_load_h1(sbase + ps * H1_STAGE, A, B, M, N, K,
                          rowBase, colBase, (c + H1_NSTG - 1) << 5, ldR, ldC);
        }

        const uint32_t sb = sbase + slot * H1_STAGE;
        if (++slot == H1_NSTG) slot = 0;
        #pragma unroll
        for (int ks = 0; ks < 32; ks += 16) {
            uint32_t ah[2][4];
            #pragma unroll
            for (int mt = 0; mt < 2; mt++) {
                const int r0 = warpM * 32 + mt * 16;
                uint32_t off = (uint32_t)((r0 + aRow) * TCSTR + ks + aColOff) * 2;
                ldmx4(sb + H1_A + off, ah[mt]);
            }
            uint32_t bh[4][4];
            #pragma unroll
            for (int nb = 0; nb < 4; nb++) {
                const int n0 = warpN * 64 + nb * 16;
                uint32_t off = (uint32_t)((n0 + bRow) * TCSTR + ks + bColOff) * 2;
                ldmx4(sb + H1_B + off, bh[nb]);
            }
            #pragma unroll
            for (int mt = 0; mt < 2; mt++) {
                #pragma unroll
                for (int nt = 0; nt < 8; nt++) {
                    const int nb = nt >> 1, hi = (nt & 1) * 2;
                    mmah(acc[mt][nt], ah[mt], bh[nb][hi], bh[nb][hi+1]);
                }
            }
        }
    }

    #pragma unroll
    for (int mt = 0; mt < 2; mt++) {
        #pragma unroll
        for (int half = 0; half < 2; half++) {
            const int row = rowBase + warpM * 32 + mt * 16 + (lane >> 2) + half * 8;
            if (row < M) {
                #pragma unroll
                for (int nt = 0; nt < 8; nt++) {
                    const int col = colBase + warpN * 64 + nt * 8 + (lane & 3) * 2;
                    float ox = acc[mt][nt][half*2+0] + bias[col];
                    float oy = acc[mt][nt][half*2+1] + bias[col+1];
                    if (RELU) { ox = fmaxf(ox, 0.f); oy = fmaxf(oy, 0.f); }
                    if (OUT == 0) {
                        *(float2*)(Cf + (size_t)row * N + col) = make_float2(ox, oy);
                    } else {
                        *(__half2*)(C16 + (size_t)row * N + col) =
                            __half2(__float2half(ox), __float2half(oy));
                    }
                }
            }
        }
    }
}

// =================== fp16 tensor-core flash self-attention (R14) ===========
#define ATT_Q 0
#define ATT_KV(st) (10240 + (st)*10240)
#define ATT_K_O 0
#define ATT_V_O 5120
#define ATT_SMEM (10240 + 2*10240)
#define KSCALE 0.25503486f   /* log2(e)/sqrt(32) */

__global__ __launch_bounds__(256)
void attn_mma(const __half* __restrict__ qk2, const __half* __restrict__ v2,
              __half* __restrict__ oh) {
    extern __shared__ char smem[];
    const uint32_t sb = smem_u32(smem);
    const int tid = threadIdx.x;
    const int lane = tid & 31;
    const int w = tid >> 5;
    const int g = lane >> 2, t4 = lane & 3;
    const int qbase = blockIdx.x * 128;
    const int b = blockIdx.y >> 3, h = blockIdx.y & 7;

    {
        const int r = tid >> 1, cb = (tid & 1) * 32;
        const int gr = qbase + r;
        const bool v = gr < LQ;
        const size_t rowo = ((size_t)(b * LQ + (v ? gr : 0)) * 512 + h * 32) * 2;
        cp16z(sb + ATT_Q + r * 80 + cb,      (const char*)qk2 + rowo + cb, v);
        cp16z(sb + ATT_Q + r * 80 + cb + 16, (const char*)qk2 + rowo + cb + 16, v);
    }
    {
        const int r = tid >> 2, j = tid & 3;
        const bool v = r < LQ;
        const size_t ko = ((size_t)(b * LQ + (v ? r : 0)) * 512 + 256 + h * 32) * 2 + j * 16;
        const size_t vo = ((size_t)(b * LQ + (v ? r : 0)) * 256 + h * 32) * 2 + j * 16;
        cp16z(sb + ATT_KV(0) + ATT_K_O + r * 80 + j * 16, (const char*)qk2 + ko, v);
        cp16z(sb + ATT_KV(0) + ATT_V_O + r * 80 + j * 16, (const char*)v2 + vo, v);
    }
    asm volatile("cp.async.commit_group;" ::: "memory");

    float m0 = -1e30f, m1 = -1e30f, l0 = 0.f, l1 = 0.f;
    float o[4][4];
    #pragma unroll
    for (int vt = 0; vt < 4; vt++)
        #pragma unroll
        for (int i = 0; i < 4; i++) o[vt][i] = 0.f;

    uint32_t qh[2][4];
    const int bRow = (lane & 7) + ((lane >> 4) & 1) * 8;
    const int bColOff = ((lane >> 3) & 1) * 8;
    const int NT = (LQ + 63) / 64;

    for (int ti = 0; ti < NT; ti++) {
        asm volatile("cp.async.wait_group 0;" ::: "memory");
        __syncthreads();
        if (ti == 0) {
            #pragma unroll
            for (int kf = 0; kf < 2; kf++) {
                uint32_t off = (uint32_t)((w * 16 + (lane & 15)) * TCSTR + kf * 16 + (lane >> 4) * 8) * 2;
                ldmx4(sb + ATT_Q + off, qh[kf]);
            }
        }
        if (ti + 1 < NT) {
            const int kt = (ti + 1) * 64;
            const int r = tid >> 2, j = tid & 3;
            const int kr = kt + r;
            const bool v = kr < LQ;
            const size_t ko = ((size_t)(b * LQ + (v ? kr : 0)) * 512 + 256 + h * 32) * 2 + j * 16;
            const size_t vo = ((size_t)(b * LQ + (v ? kr : 0)) * 256 + h * 32) * 2 + j * 16;
            const uint32_t st = sb + ATT_KV((ti + 1) & 1);
            cp16z(st + ATT_K_O + r * 80 + j * 16, (const char*)qk2 + ko, v);
            cp16z(st + ATT_V_O + r * 80 + j * 16, (const char*)v2 + vo, v);
            asm volatile("cp.async.commit_group;" ::: "memory");
        }

        const uint32_t stg = sb + ATT_KV(ti & 1);
        const int kt = ti * 64;

        float s[8][4];
        #pragma unroll
        for (int nt = 0; nt < 8; nt++)
            #pragma unroll
            for (int i = 0; i < 4; i++) s[nt][i] = 0.f;
        #pragma unroll
        for (int kf = 0; kf < 2; kf++) {
            #pragma unroll
            for (int nb = 0; nb < 4; nb++) {
                uint32_t off = (uint32_t)((nb * 16 + bRow) * TCSTR + kf * 16 + bColOff) * 2;
                uint32_t kh[4];
                ldmx4(stg + ATT_K_O + off, kh);
                #pragma unroll
                for (int hf = 0; hf < 2; hf++) {
                    mmah(s[nb * 2 + hf], qh[kf], kh[hf*2], kh[hf*2+1]);
                }
            }
        }

        const int validTiles = min(8, (LQ - kt) >> 3);
        float tmax0 = -1e30f, tmax1 = -1e30f;
        #pragma unroll
        for (int nt = 0; nt < 8; nt++) {
            if (nt < validTiles) {
                s[nt][0] *= KSCALE; s[nt][1] *= KSCALE;
                s[nt][2] *= KSCALE; s[nt][3] *= KSCALE;
            } else {
                s[nt][0] = s[nt][1] = s[nt][2] = s[nt][3] = -1e30f;
            }
            tmax0 = fmaxf(tmax0, fmaxf(s[nt][0], s[nt][1]));
            tmax1 = fmaxf(tmax1, fmaxf(s[nt][2], s[nt][3]));
        }
        tmax0 = fmaxf(tmax0, __shfl_xor_sync(0xffffffffu, tmax0, 1));
        tmax0 = fmaxf(tmax0, __shfl_xor_sync(0xffffffffu, tmax0, 2));
        tmax1 = fmaxf(tmax1, __shfl_xor_sync(0xffffffffu, tmax1, 1));
        tmax1 = fmaxf(tmax1, __shfl_xor_sync(0xffffffffu, tmax1, 2));
        const float mn0 = fmaxf(m0, tmax0), mn1 = fmaxf(m1, tmax1);
        const float c0 = ex2f(m0 - mn0), c1 = ex2f(m1 - mn1);
        m0 = mn0; m1 = mn1;
        l0 *= c0; l1 *= c1;
        #pragma unroll
        for (int vt = 0; vt < 4; vt++) {
            o[vt][0] *= c0; o[vt][1] *= c0; o[vt][2] *= c1; o[vt][3] *= c1;
        }

        uint32_t ph[4][4];
        #pragma unroll
        for (int nt = 0; nt < 8; nt++) {
            float p0 = ex2f(s[nt][0] - mn0), p1 = ex2f(s[nt][1] - mn0);
            float p2 = ex2f(s[nt][2] - mn1), p3 = ex2f(s[nt][3] - mn1);
            l0 += p0 + p1; l1 += p2 + p3;
            const int ks = nt >> 1, base = (nt & 1) * 2;
            __half2 p01(__float2half(p0), __float2half(p1));
            __half2 p23(__float2half(p2), __float2half(p3));
            ph[ks][base+0] = *(uint32_t*)&p01;
            ph[ks][base+1] = *(uint32_t*)&p23;
        }

        #pragma unroll
        for (int ks = 0; ks < 4; ks++) {
            const int krow = ks * 16 + (lane & 7) + ((lane >> 3) & 1) * 8;
            #pragma unroll
            for (int nh = 0; nh < 2; nh++) {
                uint32_t off = (uint32_t)(krow * TCSTR + nh * 16 + (lane >> 4) * 8) * 2;
                uint32_t vh[4];
                ldmx4t(stg + ATT_V_O + off, vh);
                #pragma unroll
                for (int sub = 0; sub < 2; sub++) {
                    mmah(o[nh * 2 + sub], ph[ks], vh[sub*2], vh[sub*2+1]);
                }
            }
        }
    }

    l0 += __shfl_xor_sync(0xffffffffu, l0, 1);
    l0 += __shfl_xor_sync(0xffffffffu, l0, 2);
    l1 += __shfl_xor_sync(0xffffffffu, l1, 1);
    l1 += __shfl_xor_sync(0xffffffffu, l1, 2);
    const float inv0 = 1.f / l0, inv1 = 1.f / l1;
    const int r0 = qbase + w * 16 + g;
    const int r1 = r0 + 8;
    #pragma unroll
    for (int half = 0; half < 2; half++) {
        const int row = half ? r1 : r0;
        const float inv = half ? inv1 : inv0;
        if (row < LQ) {
            const size_t base = ((size_t)(b * LQ + row)) * DM + h * DH;
            #pragma unroll
            for (int vt = 0; vt < 4; vt++) {
                float vx = o[vt][half*2+0] * inv;
                float vy = o[vt][half*2+1] * inv;
                *(__half2*)(oh + base + vt * 8 + t4 * 2) =
                    __half2(__float2half(vx), __float2half(vy));
            }
        }
    }
}

// ---------------- weight converter (fp16 single) + combined bias -----------
__global__ void cvt_weights(const float* __restrict__ w0, const float* __restrict__ w1,
                            const float* __restrict__ w2, const float* __restrict__ w3,
                            const float* __restrict__ w4, const float* __restrict__ w5,
                            const float* __restrict__ w6, const float* __restrict__ w7,
                            const float* __restrict__ off_b, const float* __restrict__ aw_b,
                            __half* __restrict__ w16, float* __restrict__ cbias) {
    int i = blockIdx.x * blockDim.x + threadIdx.x;
    if (i < 384) cbias[i] = (i < 256) ? off_b[i] : aw_b[i - 256];
    if (i >= WTOT) return;
    const float* src; int local;
    if      (i < OFF_SAOUT) { src = w0; local = i; }
    else if (i < OFF_OFFW)  { src = w1; local = i - OFF_SAOUT; }
    else if (i < OFF_VALW)  { src = (i < 327680) ? w2 : w3; local = (i < 327680) ? i - OFF_OFFW : i - 327680; }
    else if (i < OFF_OUTPW) { src = w4; local = i - OFF_VALW; }
    else if (i < OFF_FFN1)  { src = w5; local = i - OFF_OUTPW; }
    else if (i < OFF_FFN2)  { src = w6; local = i - OFF_FFN1; }
    else                    { src = w7; local = i - OFF_FFN2; }
    w16[i] = __float2half(src[local]);
}

// ---------------- add + fp16 convert ---------------------------------------
__global__ void add_cvt_kernel(const float* __restrict__ a, const float* __restrict__ b,
                               __half* __restrict__ q16, __half* __restrict__ t16, int n4) {
    int i = blockIdx.x * blockDim.x + threadIdx.x;
    if (i >= n4) return;
    float4 x = ((const float4*)a)[i];
    float4 y = ((const float4*)b)[i];
    *(__half2*)(q16 + i*4)     = __half2(__float2half(x.x + y.x), __float2half(x.y + y.y));
    *(__half2*)(q16 + i*4 + 2) = __half2(__float2half(x.z + y.z), __float2half(x.w + y.w));
    *(__half2*)(t16 + i*4)     = __half2(__float2half(x.x), __float2half(x.y));
    *(__half2*)(t16 + i*4 + 2) = __half2(__float2half(x.z), __float2half(x.w));
}

// ---------------- fp32 -> fp16 converter ------------------------------------
__global__ void cvt_f16_kernel(const float* __restrict__ a, __half* __restrict__ o, int n4) {
    int i = blockIdx.x * blockDim.x + threadIdx.x;
    if (i >= n4) return;
    float4 x = ((const float4*)a)[i];
    *(__half2*)(o + i*4)     = __half2(__float2half(x.x), __float2half(x.y));
    *(__half2*)(o + i*4 + 2) = __half2(__float2half(x.z), __float2half(x.w));
}

// ---------------- LayerNorm(x+res) -> fp32 (+ optional fp16 of out+pos) ----
__global__ __launch_bounds__(256)
void ln_kernel(const float* __restrict__ x, const float* __restrict__ res,
               const float* __restrict__ g, const float* __restrict__ bta,
               float* __restrict__ out,
               const float* __restrict__ pos, __half* __restrict__ o16) {
    __shared__ float red[8];
    const int row = blockIdx.x, t = threadIdx.x;
    const size_t idx = (size_t)row * DM + t;
    float v = x[idx] + res[idx];

    float s = v;
    #pragma unroll
    for (int o = 16; o; o >>= 1) s += __shfl_xor_sync(0xffffffffu, s, o);
    if ((t & 31) == 0) red[t >> 5] = s;
    __syncthreads();
    float mean = 0.f;
    #pragma unroll
    for (int i = 0; i < 8; i++) mean += red[i];
    mean *= (1.f / DM);
    __syncthreads();

    float d = v - mean;
    float s2 = d * d;
    #pragma unroll
    for (int o = 16; o; o >>= 1) s2 += __shfl_xor_sync(0xffffffffu, s2, o);
    if ((t & 31) == 0) red[t >> 5] = s2;
    __syncthreads();
    float var = 0.f;
    #pragma unroll
    for (int i = 0; i < 8; i++) var += red[i];
    var *= (1.f / DM);

    float o = d * rsqrtf(var + 1e-5f) * g[t] + bta[t];
    out[idx] = o;
    if (o16) {
        float tq = pos ? o + pos[idx] : o;
        o16[idx] = __float2half(tq);
    }
}

// ---------------- MS-deformable sampling (fused aw softmax, half2) ---------
__global__ __launch_bounds__(128)
void deform_kernel(const __half* __restrict__ value, const float* __restrict__ offaw,
                   const float* __restrict__ ref, __half* __restrict__ o16) {
    __shared__ float saw[8][16];
    const int qidx = blockIdx.x;
    const int b = qidx / LQ;
    const int h = threadIdx.y;          // 0..7
    const int d2 = threadIdx.x;         // 0..15

    const size_t oq = (size_t)qidx;
    const float* offp = offaw + oq * 384;

    {
        float logit = offp[256 + h * 16 + d2];
        float mx = logit;
        #pragma unroll
        for (int o = 8; o; o >>= 1) mx = fmaxf(mx, __shfl_xor_sync(0xffffffffu, mx, o));
        float e = __expf(logit - mx);
        float sm = e;
        #pragma unroll
        for (int o = 8; o; o >>= 1) sm += __shfl_xor_sync(0xffffffffu, sm, o);
        saw[h][d2] = e / sm;
    }
    __syncthreads();

    const int starts[4] = {0, 16384, 20480, 21504};
    const int Wi[4]     = {128, 64, 32, 16};

    const __half2* vb = (const __half2*)(value + (size_t)b * LEN_IN * DM + h * DH) + d2;
    float accx = 0.f, accy = 0.f;

    #pragma unroll
    for (int lvl = 0; lvl < NLV; lvl++) {
        const float W = (float)Wi[lvl];
        const int   Wl = Wi[lvl];
        const int   st = starts[lvl];
        const float rx = ref[(oq * NLV + lvl) * 2 + 0];
        const float ry = ref[(oq * NLV + lvl) * 2 + 1];
        #pragma unroll
        for (int p = 0; p < NPT; p++) {
            const int oidx = ((h * NLV + lvl) * NPT + p) * 2;
            const float ox = offp[oidx + 0];
            const float oy = offp[oidx + 1];
            const float a  = saw[h][lvl * 4 + p];
            const float x = (rx + ox / W) * W - 0.5f;
            const float y = (ry + oy / W) * W - 0.5f;
            const float x0f = floorf(x), y0f = floorf(y);
            const float lx = x - x0f, ly = y - y0f;
            const int x0 = (int)x0f, y0 = (int)y0f;

            const float w00 = a * (1.f - ly) * (1.f - lx);
            const float w01 = a * (1.f - ly) * lx;
            const float w10 = a * ly * (1.f - lx);
            const float w11 = a * ly * lx;

            const bool xv0 = (x0 >= 0) & (x0 < Wl);
            const bool xv1 = (x0 + 1 >= 0) & (x0 + 1 < Wl);
            const bool yv0 = (y0 >= 0) & (y0 < Wl);
            const bool yv1 = (y0 + 1 >= 0) & (y0 + 1 < Wl);

            if (yv0 & xv0) { float2 v = __half22float2(vb[(size_t)(st + y0 * Wl + x0) * 128]); accx = fmaf(w00, v.x, accx); accy = fmaf(w00, v.y, accy); }
            if (yv0 & xv1) { float2 v = __half22float2(vb[(size_t)(st + y0 * Wl + x0 + 1) * 128]); accx = fmaf(w01, v.x, accx); accy = fmaf(w01, v.y, accy); }
            if (yv1 & xv0) { float2 v = __half22float2(vb[(size_t)(st + (y0 + 1) * Wl + x0) * 128]); accx = fmaf(w10, v.x, accx); accy = fmaf(w10, v.y, accy); }
            if (yv1 & xv1) { float2 v = __half22float2(vb[(size_t)(st + (y0 + 1) * Wl + x0 + 1) * 128]); accx = fmaf(w11, v.x, accx); accy = fmaf(w11, v.y, accy); }
        }
    }
    *(__half2*)(o16 + oq * DM + h * DH + d2 * 2) =
        __half2(__float2half(accx), __float2half(accy));
}

// ---------------- host-side orchestration ----------------------------------
static inline void gemm_f32(const __half* A, const __half* B, const float* bias,
                            float* Cf, int M, int N, int K) {
    dim3 grid(N / 128, (M + 127) / 128);
    tc_gemm<false, 0><<<grid, 256, H1_SMEM>>>(A, B, bias, Cf, 0, M, N, K);
}
static inline void gemm_f16(const __half* A, const __half* B, const float* bias,
                            __half* C16, int M, int N, int K, bool relu) {
    dim3 grid(N / 128, (M + 127) / 128);
    if (relu) tc_gemm<true, 1><<<grid, 256, H1_SMEM>>>(A, B, bias, 0, C16, M, N, K);
    else      tc_gemm<false, 1><<<grid, 256, H1_SMEM>>>(A, B, bias, 0, C16, M, N, K);
}

extern "C" void kernel_launch(void* const* d_in, const int* in_sizes, int n_in,
                              void* d_out, int out_size) {
    (void)in_sizes; (void)n_in; (void)out_size;
    const float* tgt       = (const float*)d_in[0];
    const float* query_pos = (const float*)d_in[1];
    const float* refpts    = (const float*)d_in[2];
    const float* src       = (const float*)d_in[3];
    const float* sa_in_b   = (const float*)d_in[7];
    const float* sa_out_b  = (const float*)d_in[9];
    const float* norm2_g   = (const float*)d_in[10];
    const float* norm2_b   = (const float*)d_in[11];
    const float* off_b     = (const float*)d_in[13];
    const float* aw_b      = (const float*)d_in[15];
    const float* val_b     = (const float*)d_in[17];
    const float* outp_b    = (const float*)d_in[19];
    const float* norm1_g   = (const float*)d_in[20];
    const float* norm1_b   = (const float*)d_in[21];
    const float* ffn_b1    = (const float*)d_in[23];
    const float* ffn_b2    = (const float*)d_in[25];
    const float* norm3_g   = (const float*)d_in[26];
    const float* norm3_b   = (const float*)d_in[27];
    float* out = (float*)d_out;

    cudaFuncSetAttribute(tc_gemm<false,0>, cudaFuncAttributeMaxDynamicSharedMemorySize, H1_SMEM);
    cudaFuncSetAttribute(tc_gemm<false,1>, cudaFuncAttributeMaxDynamicSharedMemorySize, H1_SMEM);
    cudaFuncSetAttribute(tc_gemm<true,1>,  cudaFuncAttributeMaxDynamicSharedMemorySize, H1_SMEM);
    cudaFuncSetAttribute(attn_mma, cudaFuncAttributeMaxDynamicSharedMemorySize, ATT_SMEM);

    void* p;
    #define SYMF(name) cudaGetSymbolAddress(&p, name); float* name##_p = (float*)p;
    #define SYMH(name) cudaGetSymbolAddress(&p, name); __half* name##_p = (__half*)p;
    SYMF(g_proj) SYMF(g_tgt2) SYMF(g_tgt3) SYMF(g_offaw) SYMF(g_cbias)
    SYMH(g_qk16) SYMH(g_tgt16) SYMH(g_qk2) SYMH(g_v2)
    SYMH(g_att16) SYMH(g_query16) SYMH(g_tgt3_16) SYMH(g_ca16) SYMH(g_ffn16)
    SYMH(g_src16) SYMH(g_value16) SYMH(g_w16)
    #undef SYMF
    #undef SYMH

    // 0) weight + input conversions
    cvt_weights<<<(WTOT + 255)/256, 256>>>(
        (const float*)d_in[6], (const float*)d_in[8], (const float*)d_in[12],
        (const float*)d_in[14], (const float*)d_in[16], (const float*)d_in[18],
        (const float*)d_in[22], (const float*)d_in[24],
        off_b, aw_b, g_w16_p, g_cbias_p);
    const int n4 = NQ * DM / 4;
    add_cvt_kernel<<<(n4 + 255)/256, 256>>>(tgt, query_pos, g_qk16_p, g_tgt16_p, n4);
    const int ns4 = (int)((size_t)NSRC * DM / 4);
    cvt_f16_kernel<<<(ns4 + 255)/256, 256>>>(src, g_src16_p, ns4);

    // 1) self-attn
    gemm_f16(g_qk16_p, g_w16_p + OFF_SAIN, sa_in_b, g_qk2_p, NQ, 512, DM, false);
    gemm_f16(g_tgt16_p, g_w16_p + OFF_SAIN + 131072, sa_in_b + 2*DM, g_v2_p, NQ, DM, DM, false);
    attn_mma<<<dim3(8, NB * NH), 256, ATT_SMEM>>>(g_qk2_p, g_v2_p, g_att16_p);
    gemm_f32(g_att16_p, g_w16_p + OFF_SAOUT, sa_out_b, g_proj_p, NQ, DM, DM);
    ln_kernel<<<NQ, DM>>>(tgt, g_proj_p, norm2_g, norm2_b, g_tgt2_p, query_pos, g_query16_p);

    // 2) cross-attn (aw softmax fused into deform)
    gemm_f16(g_src16_p, g_w16_p + OFF_VALW, val_b, g_value16_p, NSRC, DM, DM, false);
    gemm_f32(g_query16_p, g_w16_p + OFF_OFFW, g_cbias_p, g_offaw_p, NQ, 384, DM);
    deform_kernel<<<NQ, dim3(16, 8)>>>(g_value16_p, g_offaw_p, refpts, g_ca16_p);
    gemm_f32(g_ca16_p, g_w16_p + OFF_OUTPW, outp_b, g_proj_p, NQ, DM, DM);
    ln_kernel<<<NQ, DM>>>(g_tgt2_p, g_proj_p, norm1_g, norm1_b, g_tgt3_p, nullptr, g_tgt3_16_p);

    // 3) FFN
    gemm_f16(g_tgt3_16_p, g_w16_p + OFF_FFN1, ffn_b1, g_ffn16_p, NQ, DFFN, DM, true);
    gemm_f32(g_ffn16_p, g_w16_p + OFF_FFN2, ffn_b2, g_proj_p, NQ, DM, DFFN);
    ln_kernel<<<NQ, DM>>>(g_tgt3_p, g_proj_p, norm3_g, norm3_b, out, nullptr, nullptr);
}

// round 17
// speedup vs baseline: 1.0435x; 1.0096x over previous
#include <cuda_runtime.h>
#include <cuda_fp16.h>
#include <math.h>
#include <stdint.h>

#define NB    8
#define LQ    1000
#define DM    256
#define NH    8
#define DH    32
#define NLV   4
#define NPT   4
#define LEN_IN 21760
#define DFFN  1024
#define NQ    (NB*LQ)    /* 8000 */
#define NSRC  (NB*LEN_IN) /* 174080 */

// ---------------- fp32 scratch ---------------------------------------------
__device__ float g_proj[NQ*DM];
__device__ float g_tgt2[NQ*DM];
__device__ float g_tgt3[NQ*DM];
__device__ float g_offaw[NQ*384];
__device__ float g_cbias[384];

// ---------------- fp16 scratch ----------------------------------------------
__device__ __half g_qk16[NQ*DM];
__device__ __half g_tgt16[NQ*DM];
__device__ __half g_qk2[NQ*512];
__device__ __half g_v2[NQ*DM];
__device__ __half g_att16[NQ*DM];
__device__ __half g_query16[NQ*DM];
__device__ __half g_tgt3_16[NQ*DM];
__device__ __half g_ca16[NQ*DM];
__device__ __half g_ffn16[NQ*DFFN];
__device__ __half g_src16[(size_t)NSRC*DM];
__device__ __half g_value16[(size_t)NSRC*DM];

#define WTOT 1015808
#define OFF_SAIN  0
#define OFF_SAOUT 196608
#define OFF_OFFW  262144
#define OFF_VALW  360448
#define OFF_OUTPW 425984
#define OFF_FFN1  491520
#define OFF_FFN2  753664
__device__ __half g_w16[WTOT];

// =================== helpers ===============================================
__device__ __forceinline__ uint32_t smem_u32(const void* p) {
    uint32_t a;
    asm("{ .reg .u64 t; cvta.to.shared.u64 t, %1; cvt.u32.u64 %0, t; }" : "=r"(a) : "l"(p));
    return a;
}
__device__ __forceinline__ void ldmx4(uint32_t addr, uint32_t* r) {
    asm volatile("ldmatrix.sync.aligned.m8n8.x4.shared.b16 {%0,%1,%2,%3}, [%4];"
                 : "=r"(r[0]), "=r"(r[1]), "=r"(r[2]), "=r"(r[3]) : "r"(addr));
}
__device__ __forceinline__ void ldmx4t(uint32_t addr, uint32_t* r) {
    asm volatile("ldmatrix.sync.aligned.m8n8.x4.trans.shared.b16 {%0,%1,%2,%3}, [%4];"
                 : "=r"(r[0]), "=r"(r[1]), "=r"(r[2]), "=r"(r[3]) : "r"(addr));
}
__device__ __forceinline__ void mmah(float* d, const uint32_t* a, uint32_t b0, uint32_t b1) {
    asm volatile("mma.sync.aligned.m16n8k16.row.col.f32.f16.f16.f32 "
                 "{%0,%1,%2,%3}, {%4,%5,%6,%7}, {%8,%9}, {%0,%1,%2,%3};"
                 : "+f"(d[0]), "+f"(d[1]), "+f"(d[2]), "+f"(d[3])
                 : "r"(a[0]), "r"(a[1]), "r"(a[2]), "r"(a[3]), "r"(b0), "r"(b1));
}
__device__ __forceinline__ void cp16z(uint32_t dst, const void* src, bool v) {
    asm volatile("cp.async.cg.shared.global [%0], [%1], 16, %2;"
                 :: "r"(dst), "l"(src), "r"(v ? 16 : 0));
}
__device__ __forceinline__ float ex2f(float x) {
    float r; asm("ex2.approx.ftz.f32 %0, %1;" : "=f"(r) : "f"(x)); return r;
}

#define TCSTR 40

// =================== fp16 1-term GEMM, BK=32, 3-stage ring (R14) ===========
#define H1_A 0
#define H1_B 10240
#define H1_STAGE 20480
#define H1_NSTG 3
#define H1_SMEM (H1_NSTG*H1_STAGE)

__device__ __forceinline__ void stage_load_h1(
    uint32_t sb, const __half* A, const __half* B,
    int M, int N, int K, int rowBase, int colBase, int k0, int ldR, int ldC) {
    int gr = rowBase + ldR; bool av = gr < M; if (!av) gr = 0;
    const char* pa = (const char*)(A + (size_t)gr * K + k0) + ldC;
    uint32_t da = sb + H1_A + ldR * 80 + ldC;
    cp16z(da, pa, av);        cp16z(da + 16, pa + 16, av);
    int gc = colBase + ldR; bool bv = gc < N; if (!bv) gc = 0;
    const char* pb = (const char*)(B + (size_t)gc * K + k0) + ldC;
    uint32_t db = sb + H1_B + ldR * 80 + ldC;
    cp16z(db, pb, bv);        cp16z(db + 16, pb + 16, bv);
    asm volatile("cp.async.commit_group;" ::: "memory");
}

template<bool RELU, int OUT>
__global__ __launch_bounds__(256)
void tc_gemm(const __half* __restrict__ A, const __half* __restrict__ B,
             const float* __restrict__ bias, float* __restrict__ Cf,
             __half* __restrict__ C16, int M, int N, int K) {
    extern __shared__ char smem[];
    const uint32_t sbase = smem_u32(smem);
    const int tid  = threadIdx.x;
    const int lane = tid & 31;
    const int wid  = tid >> 5;
    const int warpM = wid & 3;
    const int warpN = wid >> 2;
    const int rowBase = blockIdx.y * 128;
    const int colBase = blockIdx.x * 128;
    const int ldR = tid >> 1;
    const int ldC = (tid & 1) * 32;

    const int aRow = (lane & 15);
    const int aColOff = (lane >> 4) * 8;
    const int bRow = (lane & 7) + ((lane >> 4) & 1) * 8;
    const int bColOff = ((lane >> 3) & 1) * 8;

    float acc[2][8][4];
    #pragma unroll
    for (int mt = 0; mt < 2; mt++)
        #pragma unroll
        for (int nt = 0; nt < 8; nt++)
            #pragma unroll
            for (int i = 0; i < 4; i++) acc[mt][nt][i] = 0.f;

    const int KC = K >> 5;
    #pragma unroll
    for (int s = 0; s < H1_NSTG - 1; s++)
        if (s < KC)
            stage_load_h1(sbase + s * H1_STAGE, A, B, M, N, K,
                          rowBase, colBase, s << 5, ldR, ldC);

    int slot = 0;
    for (int c = 0; c < KC; c++) {
        asm volatile("cp.async.wait_group %0;" :: "n"(H1_NSTG - 2) : "memory");
        __syncthreads();
        if (c + H1_NSTG - 1 < KC) {
            int ps = slot + (H1_NSTG - 1); if (ps >= H1_NSTG) ps -= H1_NSTG;
            stage_load_h1(sbase + ps * H1_STAGE, A, B, M, N, K,
                          rowBase, colBase, (c + H1_NSTG - 1) << 5, ldR, ldC);
        }

        const uint32_t sb = sbase + slot * H1_STAGE;
        if (++slot == H1_NSTG) slot = 0;
        #pragma unroll
        for (int ks = 0; ks < 32; ks += 16) {
            uint32_t ah[2][4];
            #pragma unroll
            for (int mt = 0; mt < 2; mt++) {
                const int r0 = warpM * 32 + mt * 16;
                uint32_t off = (uint32_t)((r0 + aRow) * TCSTR + ks + aColOff) * 2;
                ldmx4(sb + H1_A + off, ah[mt]);
            }
            uint32_t bh[4][4];
            #pragma unroll
            for (int nb = 0; nb < 4; nb++) {
                const int n0 = warpN * 64 + nb * 16;
                uint32_t off = (uint32_t)((n0 + bRow) * TCSTR + ks + bColOff) * 2;
                ldmx4(sb + H1_B + off, bh[nb]);
            }
            #pragma unroll
            for (int mt = 0; mt < 2; mt++) {
                #pragma unroll
                for (int nt = 0; nt < 8; nt++) {
                    const int nb = nt >> 1, hi = (nt & 1) * 2;
                    mmah(acc[mt][nt], ah[mt], bh[nb][hi], bh[nb][hi+1]);
                }
            }
        }
    }

    #pragma unroll
    for (int mt = 0; mt < 2; mt++) {
        #pragma unroll
        for (int half = 0; half < 2; half++) {
            const int row = rowBase + warpM * 32 + mt * 16 + (lane >> 2) + half * 8;
            if (row < M) {
                #pragma unroll
                for (int nt = 0; nt < 8; nt++) {
                    const int col = colBase + warpN * 64 + nt * 8 + (lane & 3) * 2;
                    float ox = acc[mt][nt][half*2+0] + bias[col];
                    float oy = acc[mt][nt][half*2+1] + bias[col+1];
                    if (RELU) { ox = fmaxf(ox, 0.f); oy = fmaxf(oy, 0.f); }
                    if (OUT == 0) {
                        *(float2*)(Cf + (size_t)row * N + col) = make_float2(ox, oy);
                    } else {
                        *(__half2*)(C16 + (size_t)row * N + col) =
                            __half2(__float2half(ox), __float2half(oy));
                    }
                }
            }
        }
    }
}

// =================== fp16 tensor-core flash self-attention (R14) ===========
#define ATT_Q 0
#define ATT_KV(st) (10240 + (st)*10240)
#define ATT_K_O 0
#define ATT_V_O 5120
#define ATT_SMEM (10240 + 2*10240)
#define KSCALE 0.25503486f   /* log2(e)/sqrt(32) */

__global__ __launch_bounds__(256)
void attn_mma(const __half* __restrict__ qk2, const __half* __restrict__ v2,
              __half* __restrict__ oh) {
    extern __shared__ char smem[];
    const uint32_t sb = smem_u32(smem);
    const int tid = threadIdx.x;
    const int lane = tid & 31;
    const int w = tid >> 5;
    const int g = lane >> 2, t4 = lane & 3;
    const int qbase = blockIdx.x * 128;
    const int b = blockIdx.y >> 3, h = blockIdx.y & 7;

    {
        const int r = tid >> 1, cb = (tid & 1) * 32;
        const int gr = qbase + r;
        const bool v = gr < LQ;
        const size_t rowo = ((size_t)(b * LQ + (v ? gr : 0)) * 512 + h * 32) * 2;
        cp16z(sb + ATT_Q + r * 80 + cb,      (const char*)qk2 + rowo + cb, v);
        cp16z(sb + ATT_Q + r * 80 + cb + 16, (const char*)qk2 + rowo + cb + 16, v);
    }
    {
        const int r = tid >> 2, j = tid & 3;
        const bool v = r < LQ;
        const size_t ko = ((size_t)(b * LQ + (v ? r : 0)) * 512 + 256 + h * 32) * 2 + j * 16;
        const size_t vo = ((size_t)(b * LQ + (v ? r : 0)) * 256 + h * 32) * 2 + j * 16;
        cp16z(sb + ATT_KV(0) + ATT_K_O + r * 80 + j * 16, (const char*)qk2 + ko, v);
        cp16z(sb + ATT_KV(0) + ATT_V_O + r * 80 + j * 16, (const char*)v2 + vo, v);
    }
    asm volatile("cp.async.commit_group;" ::: "memory");

    float m0 = -1e30f, m1 = -1e30f, l0 = 0.f, l1 = 0.f;
    float o[4][4];
    #pragma unroll
    for (int vt = 0; vt < 4; vt++)
        #pragma unroll
        for (int i = 0; i < 4; i++) o[vt][i] = 0.f;

    uint32_t qh[2][4];
    const int bRow = (lane & 7) + ((lane >> 4) & 1) * 8;
    const int bColOff = ((lane >> 3) & 1) * 8;
    const int NT = (LQ + 63) / 64;

    for (int ti = 0; ti < NT; ti++) {
        asm volatile("cp.async.wait_group 0;" ::: "memory");
        __syncthreads();
        if (ti == 0) {
            #pragma unroll
            for (int kf = 0; kf < 2; kf++) {
                uint32_t off = (uint32_t)((w * 16 + (lane & 15)) * TCSTR + kf * 16 + (lane >> 4) * 8) * 2;
                ldmx4(sb + ATT_Q + off, qh[kf]);
            }
        }
        if (ti + 1 < NT) {
            const int kt = (ti + 1) * 64;
            const int r = tid >> 2, j = tid & 3;
            const int kr = kt + r;
            const bool v = kr < LQ;
            const size_t ko = ((size_t)(b * LQ + (v ? kr : 0)) * 512 + 256 + h * 32) * 2 + j * 16;
            const size_t vo = ((size_t)(b * LQ + (v ? kr : 0)) * 256 + h * 32) * 2 + j * 16;
            const uint32_t st = sb + ATT_KV((ti + 1) & 1);
            cp16z(st + ATT_K_O + r * 80 + j * 16, (const char*)qk2 + ko, v);
            cp16z(st + ATT_V_O + r * 80 + j * 16, (const char*)v2 + vo, v);
            asm volatile("cp.async.commit_group;" ::: "memory");
        }

        const uint32_t stg = sb + ATT_KV(ti & 1);
        const int kt = ti * 64;

        float s[8][4];
        #pragma unroll
        for (int nt = 0; nt < 8; nt++)
            #pragma unroll
            for (int i = 0; i < 4; i++) s[nt][i] = 0.f;
        #pragma unroll
        for (int kf = 0; kf < 2; kf++) {
            #pragma unroll
            for (int nb = 0; nb < 4; nb++) {
                uint32_t off = (uint32_t)((nb * 16 + bRow) * TCSTR + kf * 16 + bColOff) * 2;
                uint32_t kh[4];
                ldmx4(stg + ATT_K_O + off, kh);
                #pragma unroll
                for (int hf = 0; hf < 2; hf++) {
                    mmah(s[nb * 2 + hf], qh[kf], kh[hf*2], kh[hf*2+1]);
                }
            }
        }

        const int validTiles = min(8, (LQ - kt) >> 3);
        float tmax0 = -1e30f, tmax1 = -1e30f;
        #pragma unroll
        for (int nt = 0; nt < 8; nt++) {
            if (nt < validTiles) {
                s[nt][0] *= KSCALE; s[nt][1] *= KSCALE;
                s[nt][2] *= KSCALE; s[nt][3] *= KSCALE;
            } else {
                s[nt][0] = s[nt][1] = s[nt][2] = s[nt][3] = -1e30f;
            }
            tmax0 = fmaxf(tmax0, fmaxf(s[nt][0], s[nt][1]));
            tmax1 = fmaxf(tmax1, fmaxf(s[nt][2], s[nt][3]));
        }
        tmax0 = fmaxf(tmax0, __shfl_xor_sync(0xffffffffu, tmax0, 1));
        tmax0 = fmaxf(tmax0, __shfl_xor_sync(0xffffffffu, tmax0, 2));
        tmax1 = fmaxf(tmax1, __shfl_xor_sync(0xffffffffu, tmax1, 1));
        tmax1 = fmaxf(tmax1, __shfl_xor_sync(0xffffffffu, tmax1, 2));
        const float mn0 = fmaxf(m0, tmax0), mn1 = fmaxf(m1, tmax1);
        const float c0 = ex2f(m0 - mn0), c1 = ex2f(m1 - mn1);
        m0 = mn0; m1 = mn1;
        l0 *= c0; l1 *= c1;
        #pragma unroll
        for (int vt = 0; vt < 4; vt++) {
            o[vt][0] *= c0; o[vt][1] *= c0; o[vt][2] *= c1; o[vt][3] *= c1;
        }

        uint32_t ph[4][4];
        #pragma unroll
        for (int nt = 0; nt < 8; nt++) {
            float p0 = ex2f(s[nt][0] - mn0), p1 = ex2f(s[nt][1] - mn0);
            float p2 = ex2f(s[nt][2] - mn1), p3 = ex2f(s[nt][3] - mn1);
            l0 += p0 + p1; l1 += p2 + p3;
            const int ks = nt >> 1, base = (nt & 1) * 2;
            __half2 p01(__float2half(p0), __float2half(p1));
            __half2 p23(__float2half(p2), __float2half(p3));
            ph[ks][base+0] = *(uint32_t*)&p01;
            ph[ks][base+1] = *(uint32_t*)&p23;
        }

        #pragma unroll
        for (int ks = 0; ks < 4; ks++) {
            const int krow = ks * 16 + (lane & 7) + ((lane >> 3) & 1) * 8;
            #pragma unroll
            for (int nh = 0; nh < 2; nh++) {
                uint32_t off = (uint32_t)(krow * TCSTR + nh * 16 + (lane >> 4) * 8) * 2;
                uint32_t vh[4];
                ldmx4t(stg + ATT_V_O + off, vh);
                #pragma unroll
                for (int sub = 0; sub < 2; sub++) {
                    mmah(o[nh * 2 + sub], ph[ks], vh[sub*2], vh[sub*2+1]);
                }
            }
        }
    }

    l0 += __shfl_xor_sync(0xffffffffu, l0, 1);
    l0 += __shfl_xor_sync(0xffffffffu, l0, 2);
    l1 += __shfl_xor_sync(0xffffffffu, l1, 1);
    l1 += __shfl_xor_sync(0xffffffffu, l1, 2);
    const float inv0 = 1.f / l0, inv1 = 1.f / l1;
    const int r0 = qbase + w * 16 + g;
    const int r1 = r0 + 8;
    #pragma unroll
    for (int half = 0; half < 2; half++) {
        const int row = half ? r1 : r0;
        const float inv = half ? inv1 : inv0;
        if (row < LQ) {
            const size_t base = ((size_t)(b * LQ + row)) * DM + h * DH;
            #pragma unroll
            for (int vt = 0; vt < 4; vt++) {
                float vx = o[vt][half*2+0] * inv;
                float vy = o[vt][half*2+1] * inv;
                *(__half2*)(oh + base + vt * 8 + t4 * 2) =
                    __half2(__float2half(vx), __float2half(vy));
            }
        }
    }
}

// ---------------- weight converter (fp16 single) + combined bias -----------
__global__ void cvt_weights(const float* __restrict__ w0, const float* __restrict__ w1,
                            const float* __restrict__ w2, const float* __restrict__ w3,
                            const float* __restrict__ w4, const float* __restrict__ w5,
                            const float* __restrict__ w6, const float* __restrict__ w7,
                            const float* __restrict__ off_b, const float* __restrict__ aw_b,
                            __half* __restrict__ w16, float* __restrict__ cbias) {
    int i = blockIdx.x * blockDim.x + threadIdx.x;
    if (i < 384) cbias[i] = (i < 256) ? off_b[i] : aw_b[i - 256];
    if (i >= WTOT) return;
    const float* src; int local;
    if      (i < OFF_SAOUT) { src = w0; local = i; }
    else if (i < OFF_OFFW)  { src = w1; local = i - OFF_SAOUT; }
    else if (i < OFF_VALW)  { src = (i < 327680) ? w2 : w3; local = (i < 327680) ? i - OFF_OFFW : i - 327680; }
    else if (i < OFF_OUTPW) { src = w4; local = i - OFF_VALW; }
    else if (i < OFF_FFN1)  { src = w5; local = i - OFF_OUTPW; }
    else if (i < OFF_FFN2)  { src = w6; local = i - OFF_FFN1; }
    else                    { src = w7; local = i - OFF_FFN2; }
    w16[i] = __float2half(src[local]);
}

// ---------------- add + fp16 convert ---------------------------------------
__global__ void add_cvt_kernel(const float* __restrict__ a, const float* __restrict__ b,
                               __half* __restrict__ q16, __half* __restrict__ t16, int n4) {
    int i = blockIdx.x * blockDim.x + threadIdx.x;
    if (i >= n4) return;
    float4 x = ((const float4*)a)[i];
    float4 y = ((const float4*)b)[i];
    *(__half2*)(q16 + i*4)     = __half2(__float2half(x.x + y.x), __float2half(x.y + y.y));
    *(__half2*)(q16 + i*4 + 2) = __half2(__float2half(x.z + y.z), __float2half(x.w + y.w));
    *(__half2*)(t16 + i*4)     = __half2(__float2half(x.x), __float2half(x.y));
    *(__half2*)(t16 + i*4 + 2) = __half2(__float2half(x.z), __float2half(x.w));
}

// ---------------- fp32 -> fp16 converter ------------------------------------
__global__ void cvt_f16_kernel(const float* __restrict__ a, __half* __restrict__ o, int n4) {
    int i = blockIdx.x * blockDim.x + threadIdx.x;
    if (i >= n4) return;
    float4 x = ((const float4*)a)[i];
    *(__half2*)(o + i*4)     = __half2(__float2half(x.x), __float2half(x.y));
    *(__half2*)(o + i*4 + 2) = __half2(__float2half(x.z), __float2half(x.w));
}

// ---------------- LayerNorm(x+res) -> fp32 (+ optional fp16 of out+pos) ----
__global__ __launch_bounds__(256)
void ln_kernel(const float* __restrict__ x, const float* __restrict__ res,
               const float* __restrict__ g, const float* __restrict__ bta,
               float* __restrict__ out,
               const float* __restrict__ pos, __half* __restrict__ o16) {
    __shared__ float red[8];
    const int row = blockIdx.x, t = threadIdx.x;
    const size_t idx = (size_t)row * DM + t;
    float v = x[idx] + res[idx];

    float s = v;
    #pragma unroll
    for (int o = 16; o; o >>= 1) s += __shfl_xor_sync(0xffffffffu, s, o);
    if ((t & 31) == 0) red[t >> 5] = s;
    __syncthreads();
    float mean = 0.f;
    #pragma unroll
    for (int i = 0; i < 8; i++) mean += red[i];
    mean *= (1.f / DM);
    __syncthreads();

    float d = v - mean;
    float s2 = d * d;
    #pragma unroll
    for (int o = 16; o; o >>= 1) s2 += __shfl_xor_sync(0xffffffffu, s2, o);
    if ((t & 31) == 0) red[t >> 5] = s2;
    __syncthreads();
    float var = 0.f;
    #pragma unroll
    for (int i = 0; i < 8; i++) var += red[i];
    var *= (1.f / DM);

    float o = d * rsqrtf(var + 1e-5f) * g[t] + bta[t];
    out[idx] = o;
    if (o16) {
        float tq = pos ? o + pos[idx] : o;
        o16[idx] = __float2half(tq);
    }
}

// ---------------- MS-deformable sampling (fused aw softmax, half2) ---------
__global__ __launch_bounds__(128)
void deform_kernel(const __half* __restrict__ value, const float* __restrict__ offaw,
                   const float* __restrict__ ref, __half* __restrict__ o16) {
    __shared__ float saw[8][16];
    const int qidx = blockIdx.x;
    const int b = qidx / LQ;
    const int h = threadIdx.y;
    const int d2 = threadIdx.x;

    const size_t oq = (size_t)qidx;
    const float* offp = offaw + oq * 384;

    {
        float logit = offp[256 + h * 16 + d2];
        float mx = logit;
        #pragma unroll
        for (int o = 8; o; o >>= 1) mx = fmaxf(mx, __shfl_xor_sync(0xffffffffu, mx, o));
        float e = __expf(logit - mx);
        float sm = e;
        #pragma unroll
        for (int o = 8; o; o >>= 1) sm += __shfl_xor_sync(0xffffffffu, sm, o);
        saw[h][d2] = e / sm;
    }
    __syncthreads();

    const int starts[4] = {0, 16384, 20480, 21504};
    const int Wi[4]     = {128, 64, 32, 16};

    const __half2* vb = (const __half2*)(value + (size_t)b * LEN_IN * DM + h * DH) + d2;
    float accx = 0.f, accy = 0.f;

    #pragma unroll
    for (int lvl = 0; lvl < NLV; lvl++) {
        const float W = (float)Wi[lvl];
        const int   Wl = Wi[lvl];
        const int   st = starts[lvl];
        const float rx = ref[(oq * NLV + lvl) * 2 + 0];
        const float ry = ref[(oq * NLV + lvl) * 2 + 1];
        #pragma unroll
        for (int p = 0; p < NPT; p++) {
            const int oidx = ((h * NLV + lvl) * NPT + p) * 2;
            const float ox = offp[oidx + 0];
            const float oy = offp[oidx + 1];
            const float a  = saw[h][lvl * 4 + p];
            const float x = (rx + ox / W) * W - 0.5f;
            const float y = (ry + oy / W) * W - 0.5f;
            const float x0f = floorf(x), y0f = floorf(y);
            const float lx = x - x0f, ly = y - y0f;
            const int x0 = (int)x0f, y0 = (int)y0f;

            const float w00 = a * (1.f - ly) * (1.f - lx);
            const float w01 = a * (1.f - ly) * lx;
            const float w10 = a * ly * (1.f - lx);
            const float w11 = a * ly * lx;

            const bool xv0 = (x0 >= 0) & (x0 < Wl);
            const bool xv1 = (x0 + 1 >= 0) & (x0 + 1 < Wl);
            const bool yv0 = (y0 >= 0) & (y0 < Wl);
            const bool yv1 = (y0 + 1 >= 0) & (y0 + 1 < Wl);

            if (yv0 & xv0) { float2 v = __half22float2(vb[(size_t)(st + y0 * Wl + x0) * 128]); accx = fmaf(w00, v.x, accx); accy = fmaf(w00, v.y, accy); }
            if (yv0 & xv1) { float2 v = __half22float2(vb[(size_t)(st + y0 * Wl + x0 + 1) * 128]); accx = fmaf(w01, v.x, accx); accy = fmaf(w01, v.y, accy); }
            if (yv1 & xv0) { float2 v = __half22float2(vb[(size_t)(st + (y0 + 1) * Wl + x0) * 128]); accx = fmaf(w10, v.x, accx); accy = fmaf(w10, v.y, accy); }
            if (yv1 & xv1) { float2 v = __half22float2(vb[(size_t)(st + (y0 + 1) * Wl + x0 + 1) * 128]); accx = fmaf(w11, v.x, accx); accy = fmaf(w11, v.y, accy); }
        }
    }
    *(__half2*)(o16 + oq * DM + h * DH + d2 * 2) =
        __half2(__float2half(accx), __float2half(accy));
}

// ---------------- host-side orchestration ----------------------------------
static inline void gemm_f32_s(cudaStream_t s, const __half* A, const __half* B,
                              const float* bias, float* Cf, int M, int N, int K) {
    dim3 grid(N / 128, (M + 127) / 128);
    tc_gemm<false, 0><<<grid, 256, H1_SMEM, s>>>(A, B, bias, Cf, 0, M, N, K);
}
static inline void gemm_f16_s(cudaStream_t s, const __half* A, const __half* B,
                              const float* bias, __half* C16, int M, int N, int K, bool relu) {
    dim3 grid(N / 128, (M + 127) / 128);
    if (relu) tc_gemm<true, 1><<<grid, 256, H1_SMEM, s>>>(A, B, bias, 0, C16, M, N, K);
    else      tc_gemm<false, 1><<<grid, 256, H1_SMEM, s>>>(A, B, bias, 0, C16, M, N, K);
}

extern "C" void kernel_launch(void* const* d_in, const int* in_sizes, int n_in,
                              void* d_out, int out_size) {
    (void)in_sizes; (void)n_in; (void)out_size;
    const float* tgt       = (const float*)d_in[0];
    const float* query_pos = (const float*)d_in[1];
    const float* refpts    = (const float*)d_in[2];
    const float* src       = (const float*)d_in[3];
    const float* sa_in_b   = (const float*)d_in[7];
    const float* sa_out_b  = (const float*)d_in[9];
    const float* norm2_g   = (const float*)d_in[10];
    const float* norm2_b   = (const float*)d_in[11];
    const float* off_b     = (const float*)d_in[13];
    const float* aw_b      = (const float*)d_in[15];
    const float* val_b     = (const float*)d_in[17];
    const float* outp_b    = (const float*)d_in[19];
    const float* norm1_g   = (const float*)d_in[20];
    const float* norm1_b   = (const float*)d_in[21];
    const float* ffn_b1    = (const float*)d_in[23];
    const float* ffn_b2    = (const float*)d_in[25];
    const float* norm3_g   = (const float*)d_in[26];
    const float* norm3_b   = (const float*)d_in[27];
    float* out = (float*)d_out;

    cudaFuncSetAttribute(tc_gemm<false,0>, cudaFuncAttributeMaxDynamicSharedMemorySize, H1_SMEM);
    cudaFuncSetAttribute(tc_gemm<false,1>, cudaFuncAttributeMaxDynamicSharedMemorySize, H1_SMEM);
    cudaFuncSetAttribute(tc_gemm<true,1>,  cudaFuncAttributeMaxDynamicSharedMemorySize, H1_SMEM);
    cudaFuncSetAttribute(attn_mma, cudaFuncAttributeMaxDynamicSharedMemorySize, ATT_SMEM);

    void* p;
    #define SYMF(name) cudaGetSymbolAddress(&p, name); float* name##_p = (float*)p;
    #define SYMH(name) cudaGetSymbolAddress(&p, name); __half* name##_p = (__half*)p;
    SYMF(g_proj) SYMF(g_tgt2) SYMF(g_tgt3) SYMF(g_offaw) SYMF(g_cbias)
    SYMH(g_qk16) SYMH(g_tgt16) SYMH(g_qk2) SYMH(g_v2)
    SYMH(g_att16) SYMH(g_query16) SYMH(g_tgt3_16) SYMH(g_ca16) SYMH(g_ffn16)
    SYMH(g_src16) SYMH(g_value16) SYMH(g_w16)
    #undef SYMF
    #undef SYMH

    // side stream for the src->value chain (overlaps with self-attn chain)
    cudaStream_t s2;
    cudaStreamCreateWithFlags(&s2, cudaStreamNonBlocking);
    cudaEvent_t evFork, evVal;
    cudaEventCreateWithFlags(&evFork, cudaEventDisableTiming);
    cudaEventCreateWithFlags(&evVal,  cudaEventDisableTiming);

    // 0) weight conversion (needed by both branches)
    cvt_weights<<<(WTOT + 255)/256, 256>>>(
        (const float*)d_in[6], (const float*)d_in[8], (const float*)d_in[12],
        (const float*)d_in[14], (const float*)d_in[16], (const float*)d_in[18],
        (const float*)d_in[22], (const float*)d_in[24],
        off_b, aw_b, g_w16_p, g_cbias_p);
    cudaEventRecord(evFork, 0);

    // ---- branch 2 (s2): src conversion + value GEMM ----
    cudaStreamWaitEvent(s2, evFork, 0);
    const int ns4 = (int)((size_t)NSRC * DM / 4);
    cvt_f16_kernel<<<(ns4 + 255)/256, 256, 0, s2>>>(src, g_src16_p, ns4);
    gemm_f16_s(s2, g_src16_p, g_w16_p + OFF_VALW, val_b, g_value16_p, NSRC, DM, DM, false);
    cudaEventRecord(evVal, s2);

    // ---- branch 1 (default stream): self-attn chain ----
    const int n4 = NQ * DM / 4;
    add_cvt_kernel<<<(n4 + 255)/256, 256>>>(tgt, query_pos, g_qk16_p, g_tgt16_p, n4);
    gemm_f16_s(0, g_qk16_p, g_w16_p + OFF_SAIN, sa_in_b, g_qk2_p, NQ, 512, DM, false);
    gemm_f16_s(0, g_tgt16_p, g_w16_p + OFF_SAIN + 131072, sa_in_b + 2*DM, g_v2_p, NQ, DM, DM, false);
    attn_mma<<<dim3(8, NB * NH), 256, ATT_SMEM>>>(g_qk2_p, g_v2_p, g_att16_p);
    gemm_f32_s(0, g_att16_p, g_w16_p + OFF_SAOUT, sa_out_b, g_proj_p, NQ, DM, DM);
    ln_kernel<<<NQ, DM>>>(tgt, g_proj_p, norm2_g, norm2_b, g_tgt2_p, query_pos, g_query16_p);
    gemm_f32_s(0, g_query16_p, g_w16_p + OFF_OFFW, g_cbias_p, g_offaw_p, NQ, 384, DM);

    // join: deform needs value16
    cudaStreamWaitEvent(0, evVal, 0);
    deform_kernel<<<NQ, dim3(16, 8)>>>(g_value16_p, g_offaw_p, refpts, g_ca16_p);
    gemm_f32_s(0, g_ca16_p, g_w16_p + OFF_OUTPW, outp_b, g_proj_p, NQ, DM, DM);
    ln_kernel<<<NQ, DM>>>(g_tgt2_p, g_proj_p, norm1_g, norm1_b, g_tgt3_p, nullptr, g_tgt3_16_p);

    // 3) FFN
    gemm_f16_s(0, g_tgt3_16_p, g_w16_p + OFF_FFN1, ffn_b1, g_ffn16_p, NQ, DFFN, DM, true);
    gemm_f32_s(0, g_ffn16_p, g_w16_p + OFF_FFN2, ffn_b2, g_proj_p, NQ, DM, DFFN);
    ln_kernel<<<NQ, DM>>>(g_tgt3_p, g_proj_p, norm3_g, norm3_b, out, nullptr, nullptr);

    cudaEventDestroy(evFork);
    cudaEventDestroy(evVal);
    cudaStreamDestroy(s2);
}